// round 11
// baseline (speedup 1.0000x reference)
#include <cuda_runtime.h>
#include <cstdint>

#define IN_F  4096
#define OUT_F 4096
#define M_ROWS 8192

#define BM 128
#define BN 128
#define BK 32
#define KITERS (IN_F / BK)          // 128
#define STAGES 3

#define LDA 36                       // padded row stride in floats (conflict-free)
#define STAGE_FLOATS ((BM + BN) * LDA)          // 9216 floats = 36864 B
#define SMEM_BYTES (STAGES * STAGE_FLOATS * 4)  // 110592 B -> 2 CTAs/SM

// fp32 (tf32-rounded) dequantized weight scratch [OUT_F][IN_F]
__device__ float g_W[(size_t)OUT_F * IN_F];
// tf32-rounded activations [M_ROWS][IN_F]
__device__ float g_Xtf[(size_t)M_ROWS * IN_F];

// ---------------- PTX helpers ----------------
__device__ __forceinline__ uint32_t smem_u32(const void* p) {
    uint32_t a;
    asm("{ .reg .u64 t; cvta.to.shared.u64 t, %1; cvt.u32.u64 %0, t; }"
        : "=r"(a) : "l"(p));
    return a;
}

__device__ __forceinline__ void cpa16(uint32_t smem_dst, const void* gmem_src) {
    asm volatile("cp.async.cg.shared.global [%0], [%1], 16;"
                 :: "r"(smem_dst), "l"(gmem_src));
}
__device__ __forceinline__ void cpa_commit() {
    asm volatile("cp.async.commit_group;" ::: "memory");
}
#define CPA_WAIT(n) asm volatile("cp.async.wait_group %0;" :: "n"(n) : "memory")

__device__ __forceinline__ float f2tf32f(float f) {
    uint32_t u;
    asm("cvt.rna.tf32.f32 %0, %1;" : "=r"(u) : "f"(f));
    return __uint_as_float(u);
}

__device__ __forceinline__ void mma_tf32(float* c, const uint32_t* a, const uint32_t* b) {
    asm volatile(
        "mma.sync.aligned.m16n8k8.row.col.f32.tf32.tf32.f32 "
        "{%0,%1,%2,%3}, {%4,%5,%6,%7}, {%8,%9}, {%0,%1,%2,%3};"
        : "+f"(c[0]), "+f"(c[1]), "+f"(c[2]), "+f"(c[3])
        : "r"(a[0]), "r"(a[1]), "r"(a[2]), "r"(a[3]), "r"(b[0]), "r"(b[1]));
}

// ---------------- Kernel 0: pre-round X to tf32 ----------------
__global__ void xcvt_kernel(const float4* __restrict__ x, int n4) {
    float4* o = reinterpret_cast<float4*>(g_Xtf);
    for (int i = blockIdx.x * blockDim.x + threadIdx.x; i < n4;
         i += gridDim.x * blockDim.x) {
        float4 v = x[i];
        v.x = f2tf32f(v.x); v.y = f2tf32f(v.y);
        v.z = f2tf32f(v.z); v.w = f2tf32f(v.w);
        o[i] = v;
    }
}

// ---------------- Kernel 1: LUT dequant (writes tf32-rounded W) ----------------
__global__ void dequant_kernel(const int* __restrict__ qw, const float* __restrict__ lut) {
    __shared__ float l[8][16];
    int o0 = blockIdx.x * 8;
    int tid = threadIdx.x;
    if (tid < 128) l[tid >> 4][tid & 15] = f2tf32f(lut[(o0 + (tid >> 4)) * 16 + (tid & 15)]);
    __syncthreads();

    int olane = tid & 7;
    int o = o0 + olane;
    const float* lr = l[olane];
    float* wrow = g_W + (size_t)o * IN_F;

    for (int p = tid >> 3; p < IN_F / 8; p += 32) {
        uint32_t q = (uint32_t)qw[(size_t)p * OUT_F + o];
        float4 a, b;
        a.x = lr[q & 15];         a.y = lr[(q >> 4) & 15];
        a.z = lr[(q >> 8) & 15];  a.w = lr[(q >> 12) & 15];
        b.x = lr[(q >> 16) & 15]; b.y = lr[(q >> 20) & 15];
        b.z = lr[(q >> 24) & 15]; b.w = lr[(q >> 28) & 15];
        float4* d = reinterpret_cast<float4*>(wrow + p * 8);
        d[0] = a;
        d[1] = b;
    }
}

// ---------------- Kernel 2: CSR outlier add (re-round to tf32) ----------------
__global__ void outlier_kernel(const int* __restrict__ rows, const int* __restrict__ cols,
                               const float* __restrict__ vals) {
    int o = blockIdx.x * blockDim.x + threadIdx.x;
    if (o >= OUT_F) return;
    int s = rows[o], e = rows[o + 1];
    float* wrow = g_W + (size_t)o * IN_F;
    for (int j = s; j < e; j++) {
        int c = cols[j];
        wrow[c] = f2tf32f(wrow[c] + vals[j]);
    }
}

// ---------------- Kernel 3: tf32 mma.sync GEMM ----------------
// CTA tile 128x128, 256 threads (8 warps as 2Mx4N, warp tile 64x32),
// BK=32, 3-stage cp.async pipeline, 2 CTAs/SM (16 warps/SM = 4/SMSP)
// for dependency-latency hiding; regs capped at 128/thread.
__global__ void __launch_bounds__(256, 2)
gemm_kernel(const float* __restrict__ bias, float* __restrict__ Y) {
    extern __shared__ float sm[];
    uint32_t sb = smem_u32(sm);

    int tid = threadIdx.x;
    int wid = tid >> 5;
    int lid = tid & 31;
    int g = lid >> 2;               // groupID (0..7)
    int q = lid & 3;                // thread-in-group (0..3)

    int n0 = blockIdx.x * BN;
    int m0 = blockIdx.y * BM;
    int WM = (wid & 1) * 64;        // warp M offset (2 M-rows of warps)
    int WN = (wid >> 1) * 32;       // warp N offset (4 N-cols of warps)

    const float* gA0 = g_Xtf + (size_t)m0 * IN_F;
    const float* gB0 = g_W + (size_t)n0 * IN_F;

    // A: 1024 16B chunks, B: 1024 16B chunks; 256 threads -> 4 chunks each side
    auto load_tile = [&](int t) {
        int s = t % STAGES;
        uint32_t abase = sb + (uint32_t)(s * STAGE_FLOATS) * 4u;
        uint32_t bbase = abase + (uint32_t)(BM * LDA) * 4u;
        const float* gA = gA0 + t * BK;
        const float* gB = gB0 + t * BK;
#pragma unroll
        for (int j = 0; j < 4; j++) {
            int idx = tid + j * 256;       // 0..1023
            int r = idx >> 3;
            int c = idx & 7;
            uint32_t soff = (uint32_t)(r * LDA + c * 4) * 4u;
            cpa16(abase + soff, gA + (size_t)r * IN_F + c * 4);
            cpa16(bbase + soff, gB + (size_t)r * IN_F + c * 4);
        }
    };

    float acc[4][4][4];
#pragma unroll
    for (int i = 0; i < 4; i++)
#pragma unroll
        for (int j = 0; j < 4; j++)
#pragma unroll
            for (int c = 0; c < 4; c++) acc[i][j][c] = 0.0f;

    load_tile(0); cpa_commit();
    load_tile(1); cpa_commit();

#pragma unroll 1
    for (int t = 0; t < KITERS; t++) {
        int s = t % STAGES;
        CPA_WAIT(1);
        __syncthreads();

        if (t + 2 < KITERS) load_tile(t + 2);
        cpa_commit();

        const uint32_t* As = reinterpret_cast<const uint32_t*>(sm + s * STAGE_FLOATS);
        const uint32_t* Bs = As + BM * LDA;

#pragma unroll
        for (int ks = 0; ks < 4; ks++) {
            uint32_t a[4][4];
            uint32_t b[4][2];
#pragma unroll
            for (int i = 0; i < 4; i++) {
                const uint32_t* pa = As + (WM + i * 16 + g) * LDA + ks * 8 + q;
                a[i][0] = pa[0];
                a[i][1] = pa[8 * LDA];
                a[i][2] = pa[4];
                a[i][3] = pa[8 * LDA + 4];
            }
#pragma unroll
            for (int j = 0; j < 4; j++) {
                const uint32_t* pb = Bs + (WN + j * 8 + g) * LDA + ks * 8 + q;
                b[j][0] = pb[0];
                b[j][1] = pb[4];
            }
#pragma unroll
            for (int i = 0; i < 4; i++)
#pragma unroll
                for (int j = 0; j < 4; j++)
                    mma_tf32(acc[i][j], a[i], b[j]);
        }
    }

    // epilogue: bias add + fp32 stores
#pragma unroll
    for (int i = 0; i < 4; i++) {
        int mlo = m0 + WM + i * 16 + g;
        float* ylo = Y + (size_t)mlo * OUT_F + n0 + WN;
        float* yhi = ylo + (size_t)8 * OUT_F;
#pragma unroll
        for (int j = 0; j < 4; j++) {
            float2 bf = *reinterpret_cast<const float2*>(bias + n0 + WN + j * 8 + 2 * q);
            float2 v0, v1;
            v0.x = acc[i][j][0] + bf.x;
            v0.y = acc[i][j][1] + bf.y;
            v1.x = acc[i][j][2] + bf.x;
            v1.y = acc[i][j][3] + bf.y;
            *reinterpret_cast<float2*>(ylo + j * 8 + 2 * q) = v0;
            *reinterpret_cast<float2*>(yhi + j * 8 + 2 * q) = v1;
        }
    }
}

// ---------------- launch ----------------
extern "C" void kernel_launch(void* const* d_in, const int* in_sizes, int n_in,
                              void* d_out, int out_size) {
    const float* x     = (const float*)d_in[0];
    const float* lut   = (const float*)d_in[1];
    const float* bias  = (const float*)d_in[2];
    const float* ovals = (const float*)d_in[3];
    const int*   qw    = (const int*)d_in[4];
    const int*   orows = (const int*)d_in[5];
    const int*   ocols = (const int*)d_in[6];
    float* y = (float*)d_out;

    int M = in_sizes[0] / IN_F;     // 8192

    xcvt_kernel<<<1024, 256>>>(reinterpret_cast<const float4*>(x),
                               (int)((size_t)M * IN_F / 4));
    dequant_kernel<<<OUT_F / 8, 256>>>(qw, lut);
    outlier_kernel<<<(OUT_F + 127) / 128, 128>>>(orows, ocols, ovals);

    cudaFuncSetAttribute(gemm_kernel, cudaFuncAttributeMaxDynamicSharedMemorySize, SMEM_BYTES);
    dim3 grid(OUT_F / BN, M / BM);
    gemm_kernel<<<grid, 256, SMEM_BYTES>>>(bias, y);
}

// round 12
// speedup vs baseline: 1.6505x; 1.6505x over previous
#include <cuda_runtime.h>
#include <cuda_fp16.h>
#include <cstdint>

#define IN_F  4096
#define OUT_F 4096
#define M_ROWS 8192

#define BM 128
#define BN 128
#define BK 32
#define KITERS (IN_F / BK)          // 128
#define STAGES 4

#define LDH 40                       // padded row stride in halves (80 B, conflict-free)
#define STAGE_HALVES ((BM + BN) * LDH)            // 10240 halves = 20480 B
#define SMEM_BYTES (STAGES * STAGE_HALVES * 2)    // 81920 B -> 2 CTAs/SM

// fp16 dequantized weight scratch [OUT_F][IN_F]
__device__ __half g_Wh[(size_t)OUT_F * IN_F];
// fp16 activations [M_ROWS][IN_F]
__device__ __half g_Xh[(size_t)M_ROWS * IN_F];

// ---------------- PTX helpers ----------------
__device__ __forceinline__ uint32_t smem_u32(const void* p) {
    uint32_t a;
    asm("{ .reg .u64 t; cvta.to.shared.u64 t, %1; cvt.u32.u64 %0, t; }"
        : "=r"(a) : "l"(p));
    return a;
}

__device__ __forceinline__ void cpa16(uint32_t smem_dst, const void* gmem_src) {
    asm volatile("cp.async.cg.shared.global [%0], [%1], 16;"
                 :: "r"(smem_dst), "l"(gmem_src));
}
__device__ __forceinline__ void cpa_commit() {
    asm volatile("cp.async.commit_group;" ::: "memory");
}
#define CPA_WAIT(n) asm volatile("cp.async.wait_group %0;" :: "n"(n) : "memory")

__device__ __forceinline__ void mma_f16(float* c, const uint32_t* a, const uint32_t* b) {
    asm volatile(
        "mma.sync.aligned.m16n8k16.row.col.f32.f16.f16.f32 "
        "{%0,%1,%2,%3}, {%4,%5,%6,%7}, {%8,%9}, {%0,%1,%2,%3};"
        : "+f"(c[0]), "+f"(c[1]), "+f"(c[2]), "+f"(c[3])
        : "r"(a[0]), "r"(a[1]), "r"(a[2]), "r"(a[3]), "r"(b[0]), "r"(b[1]));
}

__device__ __forceinline__ uint32_t pack_h2(__half lo, __half hi) {
    __half2 h = __halves2half2(lo, hi);
    return *reinterpret_cast<uint32_t*>(&h);
}

// ---------------- Kernel 0: X fp32 -> fp16 ----------------
__global__ void xcvt_kernel(const float4* __restrict__ x, int n4) {
    uint2* o = reinterpret_cast<uint2*>(g_Xh);
    for (int i = blockIdx.x * blockDim.x + threadIdx.x; i < n4;
         i += gridDim.x * blockDim.x) {
        float4 v = x[i];
        uint2 r;
        __half2 h0 = __floats2half2_rn(v.x, v.y);
        __half2 h1 = __floats2half2_rn(v.z, v.w);
        r.x = *reinterpret_cast<uint32_t*>(&h0);
        r.y = *reinterpret_cast<uint32_t*>(&h1);
        o[i] = r;
    }
}

// ---------------- Kernel 1: LUT dequant -> fp16 W ----------------
__global__ void dequant_kernel(const int* __restrict__ qw, const float* __restrict__ lut) {
    __shared__ __half l[8][16];
    int o0 = blockIdx.x * 8;
    int tid = threadIdx.x;
    if (tid < 128) l[tid >> 4][tid & 15] = __float2half(lut[(o0 + (tid >> 4)) * 16 + (tid & 15)]);
    __syncthreads();

    int olane = tid & 7;
    int o = o0 + olane;
    const __half* lr = l[olane];
    __half* wrow = g_Wh + (size_t)o * IN_F;

    for (int p = tid >> 3; p < IN_F / 8; p += 32) {
        uint32_t q = (uint32_t)qw[(size_t)p * OUT_F + o];
        uint4 r;
        r.x = pack_h2(lr[q & 15],         lr[(q >> 4) & 15]);
        r.y = pack_h2(lr[(q >> 8) & 15],  lr[(q >> 12) & 15]);
        r.z = pack_h2(lr[(q >> 16) & 15], lr[(q >> 20) & 15]);
        r.w = pack_h2(lr[(q >> 24) & 15], lr[(q >> 28) & 15]);
        *reinterpret_cast<uint4*>(wrow + p * 8) = r;
    }
}

// ---------------- Kernel 2: CSR outlier add (fp32 math, fp16 store) ----------------
__global__ void outlier_kernel(const int* __restrict__ rows, const int* __restrict__ cols,
                               const float* __restrict__ vals) {
    int o = blockIdx.x * blockDim.x + threadIdx.x;
    if (o >= OUT_F) return;
    int s = rows[o], e = rows[o + 1];
    __half* wrow = g_Wh + (size_t)o * IN_F;
    for (int j = s; j < e; j++) {
        int c = cols[j];
        wrow[c] = __float2half(__half2float(wrow[c]) + vals[j]);
    }
}

// ---------------- Kernel 3: fp16 mma.sync GEMM (fp32 accum) ----------------
// CTA tile 128x128, 256 threads (8 warps as 2Mx4N, warp tile 64x32),
// BK=32 (2 k16-steps), 4-stage cp.async pipeline, 2 CTAs/SM.
__global__ void __launch_bounds__(256, 2)
gemm_kernel(const float* __restrict__ bias, float* __restrict__ Y) {
    extern __shared__ __half smh[];
    uint32_t sb = smem_u32(smh);

    int tid = threadIdx.x;
    int wid = tid >> 5;
    int lid = tid & 31;
    int g = lid >> 2;               // groupID (0..7)
    int q = lid & 3;                // thread-in-group (0..3)

    int n0 = blockIdx.x * BN;
    int m0 = blockIdx.y * BM;
    int WM = (wid & 1) * 64;        // warp M offset
    int WN = (wid >> 1) * 32;       // warp N offset

    const __half* gA0 = g_Xh + (size_t)m0 * IN_F;
    const __half* gB0 = g_Wh + (size_t)n0 * IN_F;

    // tile = 256 rows (A 128 + B 128) x 32 halves (64 B = 4 x 16B chunks)
    // 1024 chunks, 256 threads -> 4 chunks each
    auto load_tile = [&](int t) {
        int s = t % STAGES;
        uint32_t sbase = sb + (uint32_t)(s * STAGE_HALVES) * 2u;
#pragma unroll
        for (int j = 0; j < 4; j++) {
            int idx = tid + j * 256;        // 0..1023
            int r = idx >> 2;               // row 0..255
            int c = idx & 3;                // 16B chunk
            uint32_t soff = (uint32_t)(r * 80 + c * 16);
            const __half* src = (r < BM)
                ? gA0 + (size_t)r * IN_F + t * BK + c * 8
                : gB0 + (size_t)(r - BM) * IN_F + t * BK + c * 8;
            cpa16(sbase + soff, src);
        }
    };

    float acc[4][4][4];
#pragma unroll
    for (int i = 0; i < 4; i++)
#pragma unroll
        for (int j = 0; j < 4; j++)
#pragma unroll
            for (int c = 0; c < 4; c++) acc[i][j][c] = 0.0f;

    load_tile(0); cpa_commit();
    load_tile(1); cpa_commit();
    load_tile(2); cpa_commit();

#pragma unroll 1
    for (int t = 0; t < KITERS; t++) {
        int s = t % STAGES;
        CPA_WAIT(2);                 // tile t resident (<=2 groups in flight)
        __syncthreads();

        if (t + 3 < KITERS) load_tile(t + 3);
        cpa_commit();

        const uint32_t* As = reinterpret_cast<const uint32_t*>(smh + s * STAGE_HALVES);
        const uint32_t* Bs = As + BM * (LDH / 2);   // u32 units: row stride = 20

#pragma unroll
        for (int ks = 0; ks < 2; ks++) {            // 2 x K=16 steps
            uint32_t a[4][4];
            uint32_t b[4][2];
#pragma unroll
            for (int i = 0; i < 4; i++) {
                const uint32_t* pa = As + (WM + i * 16 + g) * 20 + ks * 8 + q;
                a[i][0] = pa[0];            // (g,   2q)
                a[i][1] = pa[160];          // (g+8, 2q)      +8 rows * 20 u32
                a[i][2] = pa[4];            // (g,   2q+8)
                a[i][3] = pa[164];          // (g+8, 2q+8)
            }
#pragma unroll
            for (int j = 0; j < 4; j++) {
                const uint32_t* pb = Bs + (WN + j * 8 + g) * 20 + ks * 8 + q;
                b[j][0] = pb[0];            // k=2q,   n=g
                b[j][1] = pb[4];            // k=2q+8, n=g
            }
#pragma unroll
            for (int i = 0; i < 4; i++)
#pragma unroll
                for (int j = 0; j < 4; j++)
                    mma_f16(acc[i][j], a[i], b[j]);
        }
    }

    // epilogue: bias add + fp32 stores
#pragma unroll
    for (int i = 0; i < 4; i++) {
        int mlo = m0 + WM + i * 16 + g;
        float* ylo = Y + (size_t)mlo * OUT_F + n0 + WN;
        float* yhi = ylo + (size_t)8 * OUT_F;
#pragma unroll
        for (int j = 0; j < 4; j++) {
            float2 bf = *reinterpret_cast<const float2*>(bias + n0 + WN + j * 8 + 2 * q);
            float2 v0, v1;
            v0.x = acc[i][j][0] + bf.x;
            v0.y = acc[i][j][1] + bf.y;
            v1.x = acc[i][j][2] + bf.x;
            v1.y = acc[i][j][3] + bf.y;
            *reinterpret_cast<float2*>(ylo + j * 8 + 2 * q) = v0;
            *reinterpret_cast<float2*>(yhi + j * 8 + 2 * q) = v1;
        }
    }
}

// ---------------- launch ----------------
extern "C" void kernel_launch(void* const* d_in, const int* in_sizes, int n_in,
                              void* d_out, int out_size) {
    const float* x     = (const float*)d_in[0];
    const float* lut   = (const float*)d_in[1];
    const float* bias  = (const float*)d_in[2];
    const float* ovals = (const float*)d_in[3];
    const int*   qw    = (const int*)d_in[4];
    const int*   orows = (const int*)d_in[5];
    const int*   ocols = (const int*)d_in[6];
    float* y = (float*)d_out;

    int M = in_sizes[0] / IN_F;     // 8192

    xcvt_kernel<<<1024, 256>>>(reinterpret_cast<const float4*>(x),
                               (int)((size_t)M * IN_F / 4));
    dequant_kernel<<<OUT_F / 8, 256>>>(qw, lut);
    outlier_kernel<<<(OUT_F + 127) / 128, 128>>>(orows, ocols, ovals);

    cudaFuncSetAttribute(gemm_kernel, cudaFuncAttributeMaxDynamicSharedMemorySize, SMEM_BYTES);
    dim3 grid(OUT_F / BN, M / BM);
    gemm_kernel<<<grid, 256, SMEM_BYTES>>>(bias, y);
}

// round 14
// speedup vs baseline: 2.1024x; 1.2738x over previous
#include <cuda_runtime.h>
#include <cuda_fp16.h>
#include <cstdint>

#define IN_F  4096
#define OUT_F 4096
#define M_ROWS 8192

#define BM 128
#define BN 128
#define BK 64
#define KITERS (IN_F / BK)          // 64
#define STAGES 3

#define STAGE_HALVES ((BM + BN) * 64)             // 16384 halves = 32768 B
#define SMEM_BYTES (STAGES * STAGE_HALVES * 2)    // 98304 B -> 2 CTAs/SM

// fp16 dequantized weight scratch [OUT_F][IN_F]
__device__ __half g_Wh[(size_t)OUT_F * IN_F];
// fp16 activations [M_ROWS][IN_F]
__device__ __half g_Xh[(size_t)M_ROWS * IN_F];

// ---------------- PTX helpers ----------------
__device__ __forceinline__ uint32_t smem_u32(const void* p) {
    uint32_t a;
    asm("{ .reg .u64 t; cvta.to.shared.u64 t, %1; cvt.u32.u64 %0, t; }"
        : "=r"(a) : "l"(p));
    return a;
}

__device__ __forceinline__ void cpa16(uint32_t smem_dst, const void* gmem_src) {
    asm volatile("cp.async.cg.shared.global [%0], [%1], 16;"
                 :: "r"(smem_dst), "l"(gmem_src));
}
__device__ __forceinline__ void cpa_commit() {
    asm volatile("cp.async.commit_group;" ::: "memory");
}
#define CPA_WAIT(n) asm volatile("cp.async.wait_group %0;" :: "n"(n) : "memory")

__device__ __forceinline__ void ldsm_x4(uint32_t* r, uint32_t addr) {
    asm volatile("ldmatrix.sync.aligned.m8n8.x4.shared.b16 {%0,%1,%2,%3}, [%4];"
                 : "=r"(r[0]), "=r"(r[1]), "=r"(r[2]), "=r"(r[3]) : "r"(addr));
}

__device__ __forceinline__ void mma_f16(float* c, const uint32_t* a,
                                        uint32_t b0, uint32_t b1) {
    asm volatile(
        "mma.sync.aligned.m16n8k16.row.col.f32.f16.f16.f32 "
        "{%0,%1,%2,%3}, {%4,%5,%6,%7}, {%8,%9}, {%0,%1,%2,%3};"
        : "+f"(c[0]), "+f"(c[1]), "+f"(c[2]), "+f"(c[3])
        : "r"(a[0]), "r"(a[1]), "r"(a[2]), "r"(a[3]), "r"(b0), "r"(b1));
}

__device__ __forceinline__ uint32_t pack_h2(__half lo, __half hi) {
    __half2 h = __halves2half2(lo, hi);
    return *reinterpret_cast<uint32_t*>(&h);
}

// ---------------- Kernel 0: X fp32 -> fp16 ----------------
__global__ void xcvt_kernel(const float4* __restrict__ x, int n4) {
    uint2* o = reinterpret_cast<uint2*>(g_Xh);
    for (int i = blockIdx.x * blockDim.x + threadIdx.x; i < n4;
         i += gridDim.x * blockDim.x) {
        float4 v = x[i];
        uint2 r;
        __half2 h0 = __floats2half2_rn(v.x, v.y);
        __half2 h1 = __floats2half2_rn(v.z, v.w);
        r.x = *reinterpret_cast<uint32_t*>(&h0);
        r.y = *reinterpret_cast<uint32_t*>(&h1);
        o[i] = r;
    }
}

// ---------------- Kernel 1: LUT dequant -> fp16 W ----------------
__global__ void dequant_kernel(const int* __restrict__ qw, const float* __restrict__ lut) {
    __shared__ __half l[8][16];
    int o0 = blockIdx.x * 8;
    int tid = threadIdx.x;
    if (tid < 128) l[tid >> 4][tid & 15] = __float2half(lut[(o0 + (tid >> 4)) * 16 + (tid & 15)]);
    __syncthreads();

    int olane = tid & 7;
    int o = o0 + olane;
    const __half* lr = l[olane];
    __half* wrow = g_Wh + (size_t)o * IN_F;

    for (int p = tid >> 3; p < IN_F / 8; p += 32) {
        uint32_t q = (uint32_t)qw[(size_t)p * OUT_F + o];
        uint4 r;
        r.x = pack_h2(lr[q & 15],         lr[(q >> 4) & 15]);
        r.y = pack_h2(lr[(q >> 8) & 15],  lr[(q >> 12) & 15]);
        r.z = pack_h2(lr[(q >> 16) & 15], lr[(q >> 20) & 15]);
        r.w = pack_h2(lr[(q >> 24) & 15], lr[(q >> 28) & 15]);
        *reinterpret_cast<uint4*>(wrow + p * 8) = r;
    }
}

// ---------------- Kernel 2: CSR outlier add (fp32 math, fp16 store) ----------------
__global__ void outlier_kernel(const int* __restrict__ rows, const int* __restrict__ cols,
                               const float* __restrict__ vals) {
    int o = blockIdx.x * blockDim.x + threadIdx.x;
    if (o >= OUT_F) return;
    int s = rows[o], e = rows[o + 1];
    __half* wrow = g_Wh + (size_t)o * IN_F;
    for (int j = s; j < e; j++) {
        int c = cols[j];
        wrow[c] = __float2half(__half2float(wrow[c]) + vals[j]);
    }
}

// ---------------- Kernel 3: fp16 mma.sync GEMM (fp32 accum) ----------------
// CTA tile 128x128, 256 threads (8 warps as 2Mx4N, warp tile 64x32),
// BK=64 (4 k16-steps), SW128-swizzled 128B rows, ldmatrix fragment loads,
// 3-stage cp.async pipeline, 2 CTAs/SM.
__global__ void __launch_bounds__(256, 2)
gemm_kernel(const float* __restrict__ bias, float* __restrict__ Y) {
    extern __shared__ __half smh[];
    uint32_t sb = smem_u32(smh);

    int tid = threadIdx.x;
    int wid = tid >> 5;
    int lid = tid & 31;
    int g = lid >> 2;               // groupID (0..7)
    int q = lid & 3;                // thread-in-group (0..3)

    int n0 = blockIdx.x * BN;
    int m0 = blockIdx.y * BM;
    int WM = (wid & 1) * 64;        // warp M offset
    int WN = (wid >> 1) * 32;       // warp N offset

    const __half* gA0 = g_Xh + (size_t)m0 * IN_F;
    const __half* gB0 = g_Wh + (size_t)n0 * IN_F;

    // ldmatrix per-thread address components.
    // Rows: A region rows 0..127, B region rows 128..255; 128 B per row, SW128.
    int lr  = lid & 15;             // row within 16-row ldsm block
    int lkb = (lid >> 4) * 16;      // 0 or 16: k-halfgroup byte offset
    uint32_t a_rt[4], a_xm[4], b_rt[2], b_xm[2];
#pragma unroll
    for (int i = 0; i < 4; i++) {
        int r = WM + i * 16 + lr;
        a_rt[i] = (uint32_t)(r * 128);
        a_xm[i] = (uint32_t)((r & 7) << 4);
    }
#pragma unroll
    for (int jp = 0; jp < 2; jp++) {
        int r = BM + WN + jp * 16 + lr;
        b_rt[jp] = (uint32_t)(r * 128);
        b_xm[jp] = (uint32_t)((r & 7) << 4);
    }

    // tile = 256 rows x 128 B = 2048 16B-chunks; 256 threads -> 8 chunks each
    auto load_tile = [&](int t) {
        int s = t % STAGES;
        uint32_t sbase = sb + (uint32_t)(s * STAGE_HALVES) * 2u;
#pragma unroll
        for (int j = 0; j < 8; j++) {
            int idx = tid + j * 256;        // 0..2047
            int r = idx >> 3;               // row 0..255
            int c = idx & 7;                // 16B chunk
            uint32_t off = (uint32_t)(r * 128 + (((c << 4)) ^ ((r & 7) << 4)));
            const __half* src = (r < BM)
                ? gA0 + (size_t)r * IN_F + t * BK + c * 8
                : gB0 + (size_t)(r - BM) * IN_F + t * BK + c * 8;
            cpa16(sbase + off, src);
        }
    };

    float acc[4][4][4];
#pragma unroll
    for (int i = 0; i < 4; i++)
#pragma unroll
        for (int j = 0; j < 4; j++)
#pragma unroll
            for (int c = 0; c < 4; c++) acc[i][j][c] = 0.0f;

    load_tile(0); cpa_commit();
    load_tile(1); cpa_commit();

#pragma unroll 1
    for (int t = 0; t < KITERS; t++) {
        int s = t % STAGES;
        CPA_WAIT(1);                 // tile t resident
        __syncthreads();

        if (t + 2 < KITERS) load_tile(t + 2);
        cpa_commit();

        uint32_t stage = sb + (uint32_t)(s * STAGE_HALVES) * 2u;

#pragma unroll
        for (int ks = 0; ks < 4; ks++) {     // 4 x K=16 steps
            uint32_t cb = (uint32_t)(lkb + ks * 32);
            uint32_t a[4][4], b2[2][4];
#pragma unroll
            for (int i = 0; i < 4; i++)
                ldsm_x4(a[i], stage + a_rt[i] + (cb ^ a_xm[i]));
#pragma unroll
            for (int jp = 0; jp < 2; jp++)
                ldsm_x4(b2[jp], stage + b_rt[jp] + (cb ^ b_xm[jp]));
#pragma unroll
            for (int i = 0; i < 4; i++) {
#pragma unroll
                for (int j = 0; j < 4; j++) {
                    int jp = j >> 1, od = j & 1;
                    mma_f16(acc[i][j], a[i], b2[jp][od], b2[jp][od + 2]);
                }
            }
        }
    }

    // epilogue: bias add + fp32 stores
#pragma unroll
    for (int i = 0; i < 4; i++) {
        int mlo = m0 + WM + i * 16 + g;
        float* ylo = Y + (size_t)mlo * OUT_F + n0 + WN;
        float* yhi = ylo + (size_t)8 * OUT_F;
#pragma unroll
        for (int j = 0; j < 4; j++) {
            float2 bf = *reinterpret_cast<const float2*>(bias + n0 + WN + j * 8 + 2 * q);
            float2 v0, v1;
            v0.x = acc[i][j][0] + bf.x;
            v0.y = acc[i][j][1] + bf.y;
            v1.x = acc[i][j][2] + bf.x;
            v1.y = acc[i][j][3] + bf.y;
            *reinterpret_cast<float2*>(ylo + j * 8 + 2 * q) = v0;
            *reinterpret_cast<float2*>(yhi + j * 8 + 2 * q) = v1;
        }
    }
}

// ---------------- launch ----------------
extern "C" void kernel_launch(void* const* d_in, const int* in_sizes, int n_in,
                              void* d_out, int out_size) {
    const float* x     = (const float*)d_in[0];
    const float* lut   = (const float*)d_in[1];
    const float* bias  = (const float*)d_in[2];
    const float* ovals = (const float*)d_in[3];
    const int*   qw    = (const int*)d_in[4];
    const int*   orows = (const int*)d_in[5];
    const int*   ocols = (const int*)d_in[6];
    float* y = (float*)d_out;

    int M = in_sizes[0] / IN_F;     // 8192

    xcvt_kernel<<<1024, 256>>>(reinterpret_cast<const float4*>(x),
                               (int)((size_t)M * IN_F / 4));
    dequant_kernel<<<OUT_F / 8, 256>>>(qw, lut);
    outlier_kernel<<<(OUT_F + 127) / 128, 128>>>(orows, ocols, ovals);

    cudaFuncSetAttribute(gemm_kernel, cudaFuncAttributeMaxDynamicSharedMemorySize, SMEM_BYTES);
    dim3 grid(OUT_F / BN, M / BM);
    gemm_kernel<<<grid, 256, SMEM_BYTES>>>(bias, y);
}